// round 1
// baseline (speedup 1.0000x reference)
#include <cuda_runtime.h>

#define NPTS   16384
#define INP    64
#define OUTP   64
#define MIDC   16
#define RAD    8
#define TILE   128
#define HALO   (TILE + 2*RAD)   // 144
#define QKV    96
#define PITCH  145
#define RPITCH 65
#define EPSC   1e-5f

// shared layout (floats):
// feat_sh  : HALO*INP          = 9216   (reused as reduction buffer, pitch 65)
// qkv_sh   : QKV*PITCH         = 13920  (transposed: [chan][halo_pos])
// W_sh     : INP*QKV           = 6144
// b_sh     : QKV               = 96
// pts_sh   : HALO*2            = 288
// cst      : 340
#define SMEM_FLOATS (HALO*INP + QKV*PITCH + INP*QKV + QKV + HALO*2 + 340)

__global__ __launch_bounds__(256, 1)
void pt_fused_kernel(const float* __restrict__ points,
                     const float* __restrict__ features,
                     const float* __restrict__ Wq,  const float* __restrict__ bq,
                     const float* __restrict__ Wk,  const float* __restrict__ bk,
                     const float* __restrict__ Wv,  const float* __restrict__ bv,
                     const float* __restrict__ Wp1,
                     const float* __restrict__ p_g, const float* __restrict__ p_b,
                     const float* __restrict__ p_m, const float* __restrict__ p_v,
                     const float* __restrict__ Wp2, const float* __restrict__ bp2,
                     const float* __restrict__ w1_g, const float* __restrict__ w1_b,
                     const float* __restrict__ w1_m, const float* __restrict__ w1_v,
                     const float* __restrict__ Ww1,
                     const float* __restrict__ w2_g, const float* __restrict__ w2_b,
                     const float* __restrict__ w2_m, const float* __restrict__ w2_v,
                     const float* __restrict__ Ww2,  const float* __restrict__ bw2,
                     float* __restrict__ out)
{
    extern __shared__ float sm[];
    float* feat_sh = sm;                          // also reduction buffer later
    float* qkv_sh  = feat_sh + HALO*INP;
    float* W_sh    = qkv_sh  + QKV*PITCH;
    float* b_sh    = W_sh    + INP*QKV;
    float* pts_sh  = b_sh    + QKV;
    float* cst     = pts_sh  + HALO*2;
    float* sWp2a = cst;          // 64  Wp2 row0
    float* sWp2b = cst + 64;     // 64  Wp2 row1
    float* sbp2  = cst + 128;    // 64
    float* sAs   = cst + 192;    // 16
    float* sBs   = cst + 208;    // 16
    float* sbps  = cst + 224;    // 16
    float* sw1s  = cst + 240;    // 16
    float* sw1b  = cst + 256;    // 16
    float* sWw1  = cst + 272;    // 32
    float* sWw2  = cst + 304;    // 16
    float* sbw2  = cst + 320;    // 8
    float* smisc = cst + 328;    // 12: Wp1[4], ps[2], pb[2], w2s[2], w2b[2]

    const int tid    = threadIdx.x;
    const int bidx   = blockIdx.x;
    const int batch  = bidx >> 7;       // 128 tiles per batch
    const int tstart = (bidx & 127) * TILE;

    // ---- load weights into shared: W_sh[k][0:16]=Wq, [16:32]=Wk, [32:96]=Wv ----
    for (int i = tid; i < INP*MIDC; i += 256) {
        int k = i >> 4, m = i & 15;
        W_sh[k*QKV + m]      = Wq[i];
        W_sh[k*QKV + 16 + m] = Wk[i];
    }
    for (int i = tid; i < INP*OUTP; i += 256) {
        int k = i >> 6, c = i & 63;
        W_sh[k*QKV + 32 + c] = Wv[i];
    }
    for (int i = tid; i < QKV; i += 256)
        b_sh[i] = (i < 16) ? bq[i] : (i < 32 ? bk[i-16] : bv[i-32]);

    // ---- halo features + coords ----
    for (int i = tid; i < HALO*INP; i += 256) {
        int h = i >> 6, k = i & 63;
        int row = batch*NPTS + ((tstart + h - RAD + NPTS) & (NPTS - 1));
        feat_sh[i] = features[row*INP + k];
    }
    for (int i = tid; i < HALO*2; i += 256) {
        int h = i >> 1, c = i & 1;
        int row = batch*NPTS + ((tstart + h - RAD + NPTS) & (NPTS - 1));
        pts_sh[i] = points[row*2 + c];
    }

    // ---- folded small constants ----
    if (tid < 64) {
        sWp2a[tid] = Wp2[tid];
        sWp2b[tid] = Wp2[64 + tid];
        sbp2[tid]  = bp2[tid];
    }
    if (tid < 16) {
        sAs[tid]  = Wp2[tid] + Wp2[16+tid] + Wp2[32+tid] + Wp2[48+tid];
        sBs[tid]  = Wp2[64+tid] + Wp2[80+tid] + Wp2[96+tid] + Wp2[112+tid];
        sbps[tid] = bp2[tid] + bp2[16+tid] + bp2[32+tid] + bp2[48+tid];
        float s = w1_g[tid] * rsqrtf(w1_v[tid] + EPSC);
        sw1s[tid] = s;
        sw1b[tid] = w1_b[tid] - w1_m[tid]*s;
        sWw1[2*tid]   = Ww1[2*tid];
        sWw1[2*tid+1] = Ww1[2*tid+1];
        sWw2[tid] = Ww2[tid];
    }
    if (tid < 8) sbw2[tid] = bw2[tid];
    if (tid < 2) {
        float s = p_g[tid] * rsqrtf(p_v[tid] + EPSC);
        smisc[4+tid] = s; smisc[6+tid] = p_b[tid] - p_m[tid]*s;
        float s2 = w2_g[tid] * rsqrtf(w2_v[tid] + EPSC);
        smisc[8+tid] = s2; smisc[10+tid] = w2_b[tid] - w2_m[tid]*s2;
    }
    if (tid < 4) smisc[tid] = Wp1[tid];
    __syncthreads();

    // ---- phase 1: q/k/v GEMM into transposed qkv_sh[c*PITCH + h] ----
    {
        const int lane = tid & 31, warp = tid >> 5;
        for (int task = warp; task < HALO*3; task += 8) {
            int p  = task / 3;
            int c  = (task % 3)*32 + lane;
            float acc = b_sh[c];
            const float* fr = feat_sh + p*INP;
            #pragma unroll
            for (int k = 0; k < INP; ++k)
                acc = fmaf(fr[k], W_sh[k*QKV + c], acc);
            qkv_sh[c*PITCH + p] = acc;
        }
    }
    __syncthreads();

    // ---- phase 2: attention (2 threads per point, 8 neighbors each) ----
    const int p    = tid & 127;
    const int half = tid >> 7;
    const int hme  = p + RAD;
    const float px = pts_sh[hme*2], py = pts_sh[hme*2 + 1];

    float q[16];
    #pragma unroll
    for (int m = 0; m < 16; ++m) q[m] = qkv_sh[m*PITCH + hme];

    float acc[64];
    #pragma unroll
    for (int c = 0; c < 64; ++c) acc[c] = 0.f;

    const float W00 = smisc[0], W01 = smisc[1], W10 = smisc[2], W11 = smisc[3];
    const float ps0 = smisc[4], ps1 = smisc[5], pb0 = smisc[6], pb1 = smisc[7];
    const float w2s0 = smisc[8], w2s1 = smisc[9], w2b0 = smisc[10], w2b1 = smisc[11];

    #pragma unroll
    for (int jj = 0; jj < 8; ++jj) {
        const int j   = half*8 + jj;
        const int off = (j < 8) ? (j - 8) : (j - 7);   // -8..-1, 1..8
        const int h   = p + RAD + off;

        const float dx = pts_sh[h*2]     - px;
        const float dy = pts_sh[h*2 + 1] - py;
        const float u0 = dx*W00 + dy*W10;
        const float u1 = dx*W01 + dy*W11;
        const float h0 = fmaxf(fmaf(u0, ps0, pb0), 0.f);
        const float h1 = fmaxf(fmaf(u1, ps1, pb1), 0.f);

        // to_w MLP
        float t0 = 0.f, t1 = 0.f;
        #pragma unroll
        for (int m = 0; m < 16; ++m) {
            float rs = fmaf(h0, sAs[m], fmaf(h1, sBs[m], sbps[m]));
            float w0 = rs + qkv_sh[(16+m)*PITCH + h] - q[m];
            float wr = fmaxf(fmaf(w0, sw1s[m], sw1b[m]), 0.f);
            t0 = fmaf(wr, sWw1[2*m],   t0);
            t1 = fmaf(wr, sWw1[2*m+1], t1);
        }
        t0 = fmaxf(fmaf(t0, w2s0, w2b0), 0.f);
        t1 = fmaxf(fmaf(t1, w2s1, w2b1), 0.f);

        float e[8], mx = -1e30f;
        #pragma unroll
        for (int c = 0; c < 8; ++c) {
            e[c] = fmaf(t0, sWw2[c], fmaf(t1, sWw2[8+c], sbw2[c]));
            mx = fmaxf(mx, e[c]);
        }
        float ssum = 0.f;
        #pragma unroll
        for (int c = 0; c < 8; ++c) { e[c] = __expf(e[c] - mx); ssum += e[c]; }
        const float inv = __fdividef(1.0f, ssum);
        #pragma unroll
        for (int c = 0; c < 8; ++c) e[c] *= inv;

        // weighted accumulate of (v + r)
        #pragma unroll
        for (int c = 0; c < 64; ++c) {
            float r = fmaf(h0, sWp2a[c], fmaf(h1, sWp2b[c], sbp2[c]));
            acc[c] = fmaf(qkv_sh[(32+c)*PITCH + h] + r, e[c & 7], acc[c]);
        }
    }

    // ---- reduce the two halves via SMEM (pitch 65 = conflict-free), write out ----
    __syncthreads();               // phase-1 reads of feat_sh fully done
    if (half == 1) {
        #pragma unroll
        for (int c = 0; c < 64; ++c) feat_sh[p*RPITCH + c] = acc[c];
    }
    __syncthreads();
    if (half == 0) {
        #pragma unroll
        for (int c = 0; c < 64; ++c) feat_sh[p*RPITCH + c] += acc[c];
    }
    __syncthreads();

    float* dst = out + (size_t)(batch*NPTS + tstart) * OUTP;  // contiguous 8192 floats
    for (int i = tid; i < TILE*OUTP; i += 256) {
        int pp = i >> 6, c = i & 63;
        dst[i] = feat_sh[pp*RPITCH + c];
    }
}

extern "C" void kernel_launch(void* const* d_in, const int* in_sizes, int n_in,
                              void* d_out, int out_size)
{
    const float* points = (const float*)d_in[0];
    const float* feats  = (const float*)d_in[1];
    const float* Wq   = (const float*)d_in[2];
    const float* bq   = (const float*)d_in[3];
    const float* Wk   = (const float*)d_in[4];
    const float* bk   = (const float*)d_in[5];
    const float* Wv   = (const float*)d_in[6];
    const float* bv   = (const float*)d_in[7];
    const float* Wp1  = (const float*)d_in[8];
    const float* p_g  = (const float*)d_in[9];
    const float* p_b  = (const float*)d_in[10];
    const float* p_m  = (const float*)d_in[11];
    const float* p_v  = (const float*)d_in[12];
    const float* Wp2  = (const float*)d_in[13];
    const float* bp2  = (const float*)d_in[14];
    const float* w1_g = (const float*)d_in[15];
    const float* w1_b = (const float*)d_in[16];
    const float* w1_m = (const float*)d_in[17];
    const float* w1_v = (const float*)d_in[18];
    const float* Ww1  = (const float*)d_in[19];
    const float* w2_g = (const float*)d_in[20];
    const float* w2_b = (const float*)d_in[21];
    const float* w2_m = (const float*)d_in[22];
    const float* w2_v = (const float*)d_in[23];
    const float* Ww2  = (const float*)d_in[24];
    const float* bw2  = (const float*)d_in[25];
    float* out = (float*)d_out;

    const int smem_bytes = SMEM_FLOATS * (int)sizeof(float);
    cudaFuncSetAttribute(pt_fused_kernel,
                         cudaFuncAttributeMaxDynamicSharedMemorySize, smem_bytes);

    const int nblocks = (4 * NPTS) / TILE;   // 512
    pt_fused_kernel<<<nblocks, 256, smem_bytes>>>(
        points, feats, Wq, bq, Wk, bk, Wv, bv, Wp1,
        p_g, p_b, p_m, p_v, Wp2, bp2,
        w1_g, w1_b, w1_m, w1_v, Ww1,
        w2_g, w2_b, w2_m, w2_v, Ww2, bw2, out);
}

// round 3
// speedup vs baseline: 1.0895x; 1.0895x over previous
#include <cuda_runtime.h>

#define NPTS   16384
#define INP    64
#define OUTP   64
#define RAD    8
#define TILE   128
#define HALO   (TILE + 2*RAD)   // 144
#define QPITCH 100              // floats; 100 mod 32 = 4 -> conflict-free float4
#define OPITCH 68               // out staging pitch
#define EPSC   1e-5f

// shared layout (floats):
// feat_sh : HALO*64  = 9216   (reused as out staging, pitch 68)
// qkv_sh  : HALO*100 = 14400  ([pos][chan]: 0..15 q, 16..31 k, 32..95 v)
// pts_sh  : HALO*2   = 288
// cst     : 432 (cA4 64, cB4 64, cE4 32, cR4 256, misc 16)
#define SMEM_FLOATS (HALO*INP + HALO*QPITCH + HALO*2 + 432)

__global__ __launch_bounds__(256, 2)
void pt_fused_kernel(const float* __restrict__ points,
                     const float* __restrict__ features,
                     const float* __restrict__ Wq,  const float* __restrict__ bq,
                     const float* __restrict__ Wk,  const float* __restrict__ bk,
                     const float* __restrict__ Wv,  const float* __restrict__ bv,
                     const float* __restrict__ Wp1,
                     const float* __restrict__ p_g, const float* __restrict__ p_b,
                     const float* __restrict__ p_m, const float* __restrict__ p_v,
                     const float* __restrict__ Wp2, const float* __restrict__ bp2,
                     const float* __restrict__ w1_g, const float* __restrict__ w1_b,
                     const float* __restrict__ w1_m, const float* __restrict__ w1_v,
                     const float* __restrict__ Ww1,
                     const float* __restrict__ w2_g, const float* __restrict__ w2_b,
                     const float* __restrict__ w2_m, const float* __restrict__ w2_v,
                     const float* __restrict__ Ww2,  const float* __restrict__ bw2,
                     float* __restrict__ out)
{
    extern __shared__ float sm[];
    float* feat_sh = sm;                       // 9216
    float* qkv_sh  = feat_sh + HALO*INP;       // 14400
    float* pts_sh  = qkv_sh  + HALO*QPITCH;    // 288
    float* cst     = pts_sh  + HALO*2;
    float4* cA4 = (float4*)(cst);        // 16: (As, Bs, bps, w1s)
    float4* cB4 = (float4*)(cst + 64);   // 16: (w1b, Ww1a, Ww1b, -)
    float4* cE4 = (float4*)(cst + 128);  // 8:  (Ww2[c], Ww2[8+c], bw2[c], -)
    float4* cR4 = (float4*)(cst + 160);  // 64: (Wp2a[c], Wp2b[c], bp2[c], -)
    float*  misc = cst + 416;            // 12

    const int tid    = threadIdx.x;
    const int bidx   = blockIdx.x;
    const int batch  = bidx >> 7;
    const int tstart = (bidx & 127) * TILE;

    // ---- stage halo features (float4, coalesced) + coords ----
    {
        const float4* fglob = (const float4*)features;
        for (int i = tid; i < HALO*16; i += 256) {
            int h = i >> 4, k4 = i & 15;
            int row = batch*NPTS + ((tstart + h - RAD) & (NPTS - 1));
            ((float4*)feat_sh)[h*16 + k4] = fglob[row*16 + k4];
        }
        const float2* pglob = (const float2*)points;
        for (int i = tid; i < HALO; i += 256) {
            int row = batch*NPTS + ((tstart + i - RAD) & (NPTS - 1));
            ((float2*)pts_sh)[i] = pglob[row];
        }
    }

    // ---- folded constants ----
    if (tid < 64)
        cR4[tid] = make_float4(Wp2[tid], Wp2[64 + tid], bp2[tid], 0.f);
    if (tid < 16) {
        float As  = Wp2[tid]    + Wp2[16+tid] + Wp2[32+tid] + Wp2[48+tid];
        float Bs  = Wp2[64+tid] + Wp2[80+tid] + Wp2[96+tid] + Wp2[112+tid];
        float bps = bp2[tid] + bp2[16+tid] + bp2[32+tid] + bp2[48+tid];
        float s   = w1_g[tid] * rsqrtf(w1_v[tid] + EPSC);
        cA4[tid] = make_float4(As, Bs, bps, s);
        cB4[tid] = make_float4(w1_b[tid] - w1_m[tid]*s, Ww1[2*tid], Ww1[2*tid+1], 0.f);
    }
    if (tid < 8) cE4[tid] = make_float4(Ww2[tid], Ww2[8 + tid], bw2[tid], 0.f);
    if (tid >= 32 && tid < 34) {
        int t = tid - 32;
        float s = p_g[t] * rsqrtf(p_v[t] + EPSC);
        misc[4+t] = s; misc[6+t] = p_b[t] - p_m[t]*s;
        float s2 = w2_g[t] * rsqrtf(w2_v[t] + EPSC);
        misc[8+t] = s2; misc[10+t] = w2_b[t] - w2_m[t]*s2;
    }
    if (tid >= 36 && tid < 40) misc[tid - 36] = Wp1[tid - 36];

    // ---- phase-1 weight preload into registers (per-lane column of W) ----
    const int warp = tid >> 5, lane = tid & 31;
    int cg, sub, npw;
    if (warp < 3)      { cg = 0; sub = warp;     npw = 3; }
    else if (warp < 6) { cg = 1; sub = warp - 3; npw = 3; }
    else               { cg = 2; sub = warp - 6; npw = 2; }
    const int c = cg*32 + lane;

    float wreg[64];
    float bias;
    if (c < 16) {
        bias = bq[c];
        #pragma unroll
        for (int k = 0; k < 64; ++k) wreg[k] = Wq[k*16 + c];
    } else if (c < 32) {
        int cc = c - 16; bias = bk[cc];
        #pragma unroll
        for (int k = 0; k < 64; ++k) wreg[k] = Wk[k*16 + cc];
    } else {
        int cc = c - 32; bias = bv[cc];
        #pragma unroll
        for (int k = 0; k < 64; ++k) wreg[k] = Wv[k*64 + cc];
    }
    __syncthreads();

    // ---- phase 1: q/k/v GEMM -> qkv_sh[p*QPITCH + c] ----
    {
        const int span = HALO / npw;
        const int pend = (sub + 1) * span;
        for (int p = sub * span; p < pend; ++p) {
            const float4* fr = (const float4*)(feat_sh + (p << 6));
            float a0 = bias, a1 = 0.f, a2 = 0.f, a3 = 0.f;
            #pragma unroll
            for (int k4 = 0; k4 < 16; ++k4) {
                float4 f = fr[k4];
                a0 = fmaf(f.x, wreg[4*k4    ], a0);
                a1 = fmaf(f.y, wreg[4*k4 + 1], a1);
                a2 = fmaf(f.z, wreg[4*k4 + 2], a2);
                a3 = fmaf(f.w, wreg[4*k4 + 3], a3);
            }
            qkv_sh[p*QPITCH + c] = (a0 + a1) + (a2 + a3);
        }
    }
    __syncthreads();

    // ---- phase 2: attention, channel-split (2 threads/point, 32 chans each) ----
    const int p    = tid & 127;
    const int half = tid >> 7;
    const int hme  = p + RAD;
    const float px = pts_sh[hme*2], py = pts_sh[hme*2 + 1];

    float q[16];
    {
        const float4* q4 = (const float4*)(qkv_sh + hme*QPITCH);
        #pragma unroll
        for (int m4 = 0; m4 < 4; ++m4) {
            float4 t = q4[m4];
            q[4*m4] = t.x; q[4*m4+1] = t.y; q[4*m4+2] = t.z; q[4*m4+3] = t.w;
        }
    }

    float acc[32];
    #pragma unroll
    for (int i = 0; i < 32; ++i) acc[i] = 0.f;

    const float W00 = misc[0], W01 = misc[1], W10 = misc[2], W11 = misc[3];
    const float ps0 = misc[4], ps1 = misc[5], pb0 = misc[6], pb1 = misc[7];
    const float w2s0 = misc[8], w2s1 = misc[9], w2b0 = misc[10], w2b1 = misc[11];

    #pragma unroll 1
    for (int jj = 0; jj < 16; ++jj) {
        const int off = jj - 8 + (jj >> 3);         // -8..-1, 1..8
        const int h   = hme + off;

        const float dx = pts_sh[h*2]     - px;
        const float dy = pts_sh[h*2 + 1] - py;
        const float u0 = dx*W00 + dy*W10;
        const float u1 = dx*W01 + dy*W11;
        const float h0 = fmaxf(fmaf(u0, ps0, pb0), 0.f);
        const float h1 = fmaxf(fmaf(u1, ps1, pb1), 0.f);

        // to_w MLP (duplicated across the two halves; 16-wide, cheap)
        float t0 = 0.f, t1 = 0.f;
        const float4* k4p = (const float4*)(qkv_sh + h*QPITCH + 16);
        #pragma unroll
        for (int m4 = 0; m4 < 4; ++m4) {
            float4 kk = k4p[m4];
            float kv[4] = {kk.x, kk.y, kk.z, kk.w};
            #pragma unroll
            for (int i = 0; i < 4; ++i) {
                int m = 4*m4 + i;
                float4 a = cA4[m];
                float4 b = cB4[m];
                float rs = fmaf(h0, a.x, fmaf(h1, a.y, a.z));
                float w0 = rs + kv[i] - q[m];
                float wr = fmaxf(fmaf(w0, a.w, b.x), 0.f);
                t0 = fmaf(wr, b.y, t0);
                t1 = fmaf(wr, b.z, t1);
            }
        }
        t0 = fmaxf(fmaf(t0, w2s0, w2b0), 0.f);
        t1 = fmaxf(fmaf(t1, w2s1, w2b1), 0.f);

        float e[8], mx = -1e30f;
        #pragma unroll
        for (int cc = 0; cc < 8; ++cc) {
            float4 ce = cE4[cc];
            e[cc] = fmaf(t0, ce.x, fmaf(t1, ce.y, ce.z));
            mx = fmaxf(mx, e[cc]);
        }
        float ssum = 0.f;
        #pragma unroll
        for (int cc = 0; cc < 8; ++cc) { e[cc] = __expf(e[cc] - mx); ssum += e[cc]; }
        const float inv = __fdividef(1.0f, ssum);
        #pragma unroll
        for (int cc = 0; cc < 8; ++cc) e[cc] *= inv;

        // weighted accumulate of (v + r) for this thread's 32 channels
        const float4* v4 = (const float4*)(qkv_sh + h*QPITCH + 32 + half*32);
        #pragma unroll
        for (int c4 = 0; c4 < 8; ++c4) {
            float4 v = v4[c4];
            int cb = half*32 + c4*4;
            float4 r0 = cR4[cb], r1 = cR4[cb+1], r2 = cR4[cb+2], r3 = cR4[cb+3];
            acc[c4*4  ] = fmaf(v.x + fmaf(h0, r0.x, fmaf(h1, r0.y, r0.z)), e[(c4*4  ) & 7], acc[c4*4  ]);
            acc[c4*4+1] = fmaf(v.y + fmaf(h0, r1.x, fmaf(h1, r1.y, r1.z)), e[(c4*4+1) & 7], acc[c4*4+1]);
            acc[c4*4+2] = fmaf(v.z + fmaf(h0, r2.x, fmaf(h1, r2.y, r2.z)), e[(c4*4+2) & 7], acc[c4*4+2]);
            acc[c4*4+3] = fmaf(v.w + fmaf(h0, r3.x, fmaf(h1, r3.y, r3.z)), e[(c4*4+3) & 7], acc[c4*4+3]);
        }
    }

    // ---- stage (pitch 68 -> conflict-free) and coalesced write-out ----
    {
        float4* st = (float4*)(feat_sh + p*OPITCH + half*32);
        #pragma unroll
        for (int c4 = 0; c4 < 8; ++c4)
            st[c4] = make_float4(acc[c4*4], acc[c4*4+1], acc[c4*4+2], acc[c4*4+3]);
    }
    __syncthreads();
    {
        float4* dst = (float4*)(out + (size_t)(batch*NPTS + tstart) * OUTP);
        for (int i = tid; i < TILE*16; i += 256) {
            int pp = i >> 4, k4 = i & 15;
            dst[i] = ((const float4*)(feat_sh + pp*OPITCH))[k4];
        }
    }
}

extern "C" void kernel_launch(void* const* d_in, const int* in_sizes, int n_in,
                              void* d_out, int out_size)
{
    const float* points = (const float*)d_in[0];
    const float* feats  = (const float*)d_in[1];
    const float* Wq   = (const float*)d_in[2];
    const float* bq   = (const float*)d_in[3];
    const float* Wk   = (const float*)d_in[4];
    const float* bk   = (const float*)d_in[5];
    const float* Wv   = (const float*)d_in[6];
    const float* bv   = (const float*)d_in[7];
    const float* Wp1  = (const float*)d_in[8];
    const float* p_g  = (const float*)d_in[9];
    const float* p_b  = (const float*)d_in[10];
    const float* p_m  = (const float*)d_in[11];
    const float* p_v  = (const float*)d_in[12];
    const float* Wp2  = (const float*)d_in[13];
    const float* bp2  = (const float*)d_in[14];
    const float* w1_g = (const float*)d_in[15];
    const float* w1_b = (const float*)d_in[16];
    const float* w1_m = (const float*)d_in[17];
    const float* w1_v = (const float*)d_in[18];
    const float* Ww1  = (const float*)d_in[19];
    const float* w2_g = (const float*)d_in[20];
    const float* w2_b = (const float*)d_in[21];
    const float* w2_m = (const float*)d_in[22];
    const float* w2_v = (const float*)d_in[23];
    const float* Ww2  = (const float*)d_in[24];
    const float* bw2  = (const float*)d_in[25];
    float* out = (float*)d_out;

    const int smem_bytes = SMEM_FLOATS * (int)sizeof(float);  // ~97.3 KB
    cudaFuncSetAttribute(pt_fused_kernel,
                         cudaFuncAttributeMaxDynamicSharedMemorySize, smem_bytes);

    const int nblocks = (4 * NPTS) / TILE;   // 512
    pt_fused_kernel<<<nblocks, 256, smem_bytes>>>(
        points, feats, Wq, bq, Wk, bk, Wv, bv, Wp1,
        p_g, p_b, p_m, p_v, Wp2, bp2,
        w1_g, w1_b, w1_m, w1_v, Ww1,
        w2_g, w2_b, w2_m, w2_v, Ww2, bw2, out);
}

// round 4
// speedup vs baseline: 1.4664x; 1.3459x over previous
#include <cuda_runtime.h>

#define NPTS   16384
#define INP    64
#define OUTP   64
#define RAD    8
#define TILE   128
#define HALO   (TILE + 2*RAD)   // 144
#define QPITCH 100              // 100 mod 32 = 4 -> conflict-free float4 across lanes
#define OPITCH 68
#define EPSC   1e-5f

// cst layout (floats): [0:32) cM2(As',Bs') [32:64) cW2(Ww1 pairs) [64:80) cP0
// [80:96) cS [96:128) cE4 [128:384) cR4 [384:396) misc
#define SMEM_FLOATS (HALO*INP + HALO*QPITCH + HALO*2 + 396)

__global__ __launch_bounds__(256, 2)
void pt_fused_kernel(const float* __restrict__ points,
                     const float* __restrict__ features,
                     const float* __restrict__ Wq,  const float* __restrict__ bq,
                     const float* __restrict__ Wk,  const float* __restrict__ bk,
                     const float* __restrict__ Wv,  const float* __restrict__ bv,
                     const float* __restrict__ Wp1,
                     const float* __restrict__ p_g, const float* __restrict__ p_b,
                     const float* __restrict__ p_m, const float* __restrict__ p_v,
                     const float* __restrict__ Wp2, const float* __restrict__ bp2,
                     const float* __restrict__ w1_g, const float* __restrict__ w1_b,
                     const float* __restrict__ w1_m, const float* __restrict__ w1_v,
                     const float* __restrict__ Ww1,
                     const float* __restrict__ w2_g, const float* __restrict__ w2_b,
                     const float* __restrict__ w2_m, const float* __restrict__ w2_v,
                     const float* __restrict__ Ww2,  const float* __restrict__ bw2,
                     float* __restrict__ out)
{
    extern __shared__ float sm[];
    float* feat_sh = sm;                       // 9216 (reused as out staging)
    float* qkv_sh  = feat_sh + HALO*INP;       // 14400
    float* pts_sh  = qkv_sh  + HALO*QPITCH;    // 288
    float* cst     = pts_sh  + HALO*2;
    float2* cM2  = (float2*)(cst);        // 16: (As*s, Bs*s)
    float2* cW2  = (float2*)(cst + 32);   // 16: (Ww1a, Ww1b)
    float*  cP0  = cst + 64;              // 16: bps*s + w1b_eff
    float*  cS   = cst + 80;              // 16: s
    float4* cE4  = (float4*)(cst + 96);   // 8:  (Ww2a, Ww2b, bw2, -)
    float4* cR4  = (float4*)(cst + 128);  // 64: (Wp2a, Wp2b, bp2, -)
    float*  misc = cst + 384;             // 12

    const int tid    = threadIdx.x;
    const int bidx   = blockIdx.x;
    const int batch  = bidx >> 7;
    const int tstart = (bidx & 127) * TILE;

    // ---- stage halo features + coords ----
    {
        const float4* fglob = (const float4*)features;
        for (int i = tid; i < HALO*16; i += 256) {
            int h = i >> 4, k4 = i & 15;
            int row = batch*NPTS + ((tstart + h - RAD) & (NPTS - 1));
            ((float4*)feat_sh)[h*16 + k4] = fglob[row*16 + k4];
        }
        const float2* pglob = (const float2*)points;
        for (int i = tid; i < HALO; i += 256) {
            int row = batch*NPTS + ((tstart + i - RAD) & (NPTS - 1));
            ((float2*)pts_sh)[i] = pglob[row];
        }
    }

    // ---- folded constants ----
    if (tid < 64)
        cR4[tid] = make_float4(Wp2[tid], Wp2[64 + tid], bp2[tid], 0.f);
    if (tid < 16) {
        float As  = Wp2[tid]    + Wp2[16+tid] + Wp2[32+tid] + Wp2[48+tid];
        float Bs  = Wp2[64+tid] + Wp2[80+tid] + Wp2[96+tid] + Wp2[112+tid];
        float bps = bp2[tid] + bp2[16+tid] + bp2[32+tid] + bp2[48+tid];
        float s   = w1_g[tid] * rsqrtf(w1_v[tid] + EPSC);
        float w1beff = w1_b[tid] - w1_m[tid]*s;
        cM2[tid] = make_float2(As*s, Bs*s);
        cW2[tid] = make_float2(Ww1[2*tid], Ww1[2*tid+1]);
        cP0[tid] = bps*s + w1beff;
        cS[tid]  = s;
    }
    if (tid < 8) cE4[tid] = make_float4(Ww2[tid], Ww2[8 + tid], bw2[tid], 0.f);
    if (tid >= 32 && tid < 34) {
        int t = tid - 32;
        float s = p_g[t] * rsqrtf(p_v[t] + EPSC);
        misc[4+t] = s; misc[6+t] = p_b[t] - p_m[t]*s;
        float s2 = w2_g[t] * rsqrtf(w2_v[t] + EPSC);
        misc[8+t] = s2; misc[10+t] = w2_b[t] - w2_m[t]*s2;
    }
    if (tid >= 36 && tid < 40) misc[tid - 36] = Wp1[tid - 36];

    // ---- phase-1 weight preload (per-lane channel column) ----
    const int warp = tid >> 5, lane = tid & 31;
    int cg, sub, npw;
    if (warp < 3)      { cg = 0; sub = warp;     npw = 3; }
    else if (warp < 6) { cg = 1; sub = warp - 3; npw = 3; }
    else               { cg = 2; sub = warp - 6; npw = 2; }
    const int c = cg*32 + lane;

    float wreg[64];
    float bias;
    if (c < 16) {
        bias = bq[c];
        #pragma unroll
        for (int k = 0; k < 64; ++k) wreg[k] = Wq[k*16 + c];
    } else if (c < 32) {
        int cc = c - 16; bias = bk[cc];
        #pragma unroll
        for (int k = 0; k < 64; ++k) wreg[k] = Wk[k*16 + cc];
    } else {
        int cc = c - 32; bias = bv[cc];
        #pragma unroll
        for (int k = 0; k < 64; ++k) wreg[k] = Wv[k*64 + cc];
    }
    __syncthreads();

    // scale for q/k channels (fold BN mult of to_w input into q,k)
    const float chan_scale = (c < 32) ? cS[c & 15] : 1.0f;

    // ---- phase 1: q/k/v GEMM -> qkv_sh[p*QPITCH + c] (q,k pre-scaled) ----
    {
        const int span = HALO / npw;
        const int pend = (sub + 1) * span;
        for (int p = sub * span; p < pend; ++p) {
            const float4* fr = (const float4*)(feat_sh + (p << 6));
            float a0 = bias, a1 = 0.f, a2 = 0.f, a3 = 0.f;
            #pragma unroll
            for (int k4 = 0; k4 < 16; ++k4) {
                float4 f = fr[k4];
                a0 = fmaf(f.x, wreg[4*k4    ], a0);
                a1 = fmaf(f.y, wreg[4*k4 + 1], a1);
                a2 = fmaf(f.z, wreg[4*k4 + 2], a2);
                a3 = fmaf(f.w, wreg[4*k4 + 3], a3);
            }
            qkv_sh[p*QPITCH + c] = ((a0 + a1) + (a2 + a3)) * chan_scale;
        }
    }
    __syncthreads();

    // ---- phase 2: attention (channel-split, 2 threads/point) ----
    const int p    = tid & 127;
    const int half = tid >> 7;
    const int hme  = p + RAD;
    const float px = pts_sh[hme*2], py = pts_sh[hme*2 + 1];

    // per-point MLP constant: P[m] = cP0[m] - q'[m]
    float P[16];
    {
        const float4* q4 = (const float4*)(qkv_sh + hme*QPITCH);
        #pragma unroll
        for (int m4 = 0; m4 < 4; ++m4) {
            float4 t = q4[m4];
            P[4*m4  ] = cP0[4*m4  ] - t.x;
            P[4*m4+1] = cP0[4*m4+1] - t.y;
            P[4*m4+2] = cP0[4*m4+2] - t.z;
            P[4*m4+3] = cP0[4*m4+3] - t.w;
        }
    }

    float vacc[32];
    #pragma unroll
    for (int i = 0; i < 32; ++i) vacc[i] = 0.f;
    float S0[8], S1[8], SE[8];
    #pragma unroll
    for (int i = 0; i < 8; ++i) { S0[i] = 0.f; S1[i] = 0.f; SE[i] = 0.f; }

    const float W00 = misc[0], W01 = misc[1], W10 = misc[2], W11 = misc[3];
    const float ps0 = misc[4], ps1 = misc[5], pb0 = misc[6], pb1 = misc[7];
    const float w2s0 = misc[8], w2s1 = misc[9], w2b0 = misc[10], w2b1 = misc[11];

    #pragma unroll 1
    for (int jj = 0; jj < 16; ++jj) {
        const int off = jj - 8 + (jj >> 3);         // -8..-1, 1..8
        const int h   = hme + off;

        const float dx = pts_sh[h*2]     - px;
        const float dy = pts_sh[h*2 + 1] - py;
        const float u0 = dx*W00 + dy*W10;
        const float u1 = dx*W01 + dy*W11;
        const float h0 = fmaxf(fmaf(u0, ps0, pb0), 0.f);
        const float h1 = fmaxf(fmaf(u1, ps1, pb1), 0.f);

        // to_w MLP: arg_m = h0*As'_m + h1*Bs'_m + (k'_m + P_m)
        float t0a = 0.f, t0b = 0.f, t1a = 0.f, t1b = 0.f;
        const float4* k4p = (const float4*)(qkv_sh + h*QPITCH + 16);
        const float4* m4p = (const float4*)cM2;   // (As'_{2j},Bs'_{2j},As'_{2j+1},Bs'_{2j+1})
        const float4* w4p = (const float4*)cW2;
        #pragma unroll
        for (int m4 = 0; m4 < 4; ++m4) {
            float4 kk = m4p ? k4p[m4] : make_float4(0,0,0,0);
            float4 ma = m4p[2*m4], mb = m4p[2*m4+1];
            float4 wa = w4p[2*m4], wb = w4p[2*m4+1];
            int mb0 = 4*m4;
            float wr0 = fmaxf(fmaf(h0, ma.x, fmaf(h1, ma.y, kk.x + P[mb0  ])), 0.f);
            float wr1 = fmaxf(fmaf(h0, ma.z, fmaf(h1, ma.w, kk.y + P[mb0+1])), 0.f);
            float wr2 = fmaxf(fmaf(h0, mb.x, fmaf(h1, mb.y, kk.z + P[mb0+2])), 0.f);
            float wr3 = fmaxf(fmaf(h0, mb.z, fmaf(h1, mb.w, kk.w + P[mb0+3])), 0.f);
            t0a = fmaf(wr0, wa.x, t0a);  t1a = fmaf(wr0, wa.y, t1a);
            t0b = fmaf(wr1, wa.z, t0b);  t1b = fmaf(wr1, wa.w, t1b);
            t0a = fmaf(wr2, wb.x, t0a);  t1a = fmaf(wr2, wb.y, t1a);
            t0b = fmaf(wr3, wb.z, t0b);  t1b = fmaf(wr3, wb.w, t1b);
        }
        float t0 = t0a + t0b, t1 = t1a + t1b;
        t0 = fmaxf(fmaf(t0, w2s0, w2b0), 0.f);
        t1 = fmaxf(fmaf(t1, w2s1, w2b1), 0.f);

        float e[8];
        #pragma unroll
        for (int cc = 0; cc < 8; ++cc) {
            float4 ce = cE4[cc];
            e[cc] = fmaf(t0, ce.x, fmaf(t1, ce.y, ce.z));
        }
        float mx = fmaxf(fmaxf(fmaxf(e[0],e[1]), fmaxf(e[2],e[3])),
                         fmaxf(fmaxf(e[4],e[5]), fmaxf(e[6],e[7])));
        #pragma unroll
        for (int cc = 0; cc < 8; ++cc) e[cc] = __expf(e[cc] - mx);
        float sA = (e[0]+e[1]) + (e[2]+e[3]);
        float sB = (e[4]+e[5]) + (e[6]+e[7]);
        const float inv = __fdividef(1.0f, sA + sB);
        #pragma unroll
        for (int cc = 0; cc < 8; ++cc) e[cc] *= inv;

        // scalar sums for the factored positional term
        #pragma unroll
        for (int cc = 0; cc < 8; ++cc) {
            S0[cc] = fmaf(h0, e[cc], S0[cc]);
            S1[cc] = fmaf(h1, e[cc], S1[cc]);
            SE[cc] += e[cc];
        }

        // weighted accumulate of v only
        const float4* v4 = (const float4*)(qkv_sh + h*QPITCH + 32 + half*32);
        #pragma unroll
        for (int c4 = 0; c4 < 8; ++c4) {
            float4 v = v4[c4];
            vacc[c4*4  ] = fmaf(v.x, e[(c4*4  ) & 7], vacc[c4*4  ]);
            vacc[c4*4+1] = fmaf(v.y, e[(c4*4+1) & 7], vacc[c4*4+1]);
            vacc[c4*4+2] = fmaf(v.z, e[(c4*4+2) & 7], vacc[c4*4+2]);
            vacc[c4*4+3] = fmaf(v.w, e[(c4*4+3) & 7], vacc[c4*4+3]);
        }
    }

    // ---- apply factored positional term once, stage, write out ----
    __syncthreads();      // feat_sh reads (phase 1) complete before overwrite
    {
        float4* st = (float4*)(feat_sh + p*OPITCH + half*32);
        #pragma unroll
        for (int c4 = 0; c4 < 8; ++c4) {
            int cb = half*32 + c4*4;
            float4 r0 = cR4[cb], r1 = cR4[cb+1], r2 = cR4[cb+2], r3 = cR4[cb+3];
            float o0 = vacc[c4*4  ] + fmaf(r0.x, S0[(c4*4  )&7], fmaf(r0.y, S1[(c4*4  )&7], r0.z*SE[(c4*4  )&7]));
            float o1 = vacc[c4*4+1] + fmaf(r1.x, S0[(c4*4+1)&7], fmaf(r1.y, S1[(c4*4+1)&7], r1.z*SE[(c4*4+1)&7]));
            float o2 = vacc[c4*4+2] + fmaf(r2.x, S0[(c4*4+2)&7], fmaf(r2.y, S1[(c4*4+2)&7], r2.z*SE[(c4*4+2)&7]));
            float o3 = vacc[c4*4+3] + fmaf(r3.x, S0[(c4*4+3)&7], fmaf(r3.y, S1[(c4*4+3)&7], r3.z*SE[(c4*4+3)&7]));
            st[c4] = make_float4(o0, o1, o2, o3);
        }
    }
    __syncthreads();
    {
        float4* dst = (float4*)(out + (size_t)(batch*NPTS + tstart) * OUTP);
        for (int i = tid; i < TILE*16; i += 256) {
            int pp = i >> 4, k4 = i & 15;
            dst[i] = ((const float4*)(feat_sh + pp*OPITCH))[k4];
        }
    }
}

extern "C" void kernel_launch(void* const* d_in, const int* in_sizes, int n_in,
                              void* d_out, int out_size)
{
    const float* points = (const float*)d_in[0];
    const float* feats  = (const float*)d_in[1];
    const float* Wq   = (const float*)d_in[2];
    const float* bq   = (const float*)d_in[3];
    const float* Wk   = (const float*)d_in[4];
    const float* bk   = (const float*)d_in[5];
    const float* Wv   = (const float*)d_in[6];
    const float* bv   = (const float*)d_in[7];
    const float* Wp1  = (const float*)d_in[8];
    const float* p_g  = (const float*)d_in[9];
    const float* p_b  = (const float*)d_in[10];
    const float* p_m  = (const float*)d_in[11];
    const float* p_v  = (const float*)d_in[12];
    const float* Wp2  = (const float*)d_in[13];
    const float* bp2  = (const float*)d_in[14];
    const float* w1_g = (const float*)d_in[15];
    const float* w1_b = (const float*)d_in[16];
    const float* w1_m = (const float*)d_in[17];
    const float* w1_v = (const float*)d_in[18];
    const float* Ww1  = (const float*)d_in[19];
    const float* w2_g = (const float*)d_in[20];
    const float* w2_b = (const float*)d_in[21];
    const float* w2_m = (const float*)d_in[22];
    const float* w2_v = (const float*)d_in[23];
    const float* Ww2  = (const float*)d_in[24];
    const float* bw2  = (const float*)d_in[25];
    float* out = (float*)d_out;

    const int smem_bytes = SMEM_FLOATS * (int)sizeof(float);  // ~97.2 KB
    cudaFuncSetAttribute(pt_fused_kernel,
                         cudaFuncAttributeMaxDynamicSharedMemorySize, smem_bytes);

    const int nblocks = (4 * NPTS) / TILE;   // 512
    pt_fused_kernel<<<nblocks, 256, smem_bytes>>>(
        points, feats, Wq, bq, Wk, bk, Wv, bv, Wp1,
        p_g, p_b, p_m, p_v, Wp2, bp2,
        w1_g, w1_b, w1_m, w1_v, Ww1,
        w2_g, w2_b, w2_m, w2_v, Ww2, bw2, out);
}

// round 5
// speedup vs baseline: 2.1827x; 1.4884x over previous
#include <cuda_runtime.h>

#define NPTS   16384
#define RAD    8
#define TILE   128
#define HALO   (TILE + 2*RAD)   // 144
#define QPITCH 100              // conflict-free float4 (100 mod 32 = 4)
#define OPITCH 68
#define SPITCH 49               // S-exchange pitch, gcd(17,32)=1 -> conflict-free
#define EPSC   1e-5f
#define L2E    1.44269504088896340736f

// scratch (9216 floats): features (phase1) -> e_sh [cc*1024+jr*128+p] (phase2)
//                        -> S-exchange (pitch 49) -> out staging (pitch 68)
#define SMEM_FLOATS (HALO*64 + HALO*QPITCH + HALO*2 + 396)

#define PACK2(dst, lo, hi) asm("mov.b64 %0, {%1, %2};" : "=l"(dst) : "f"(lo), "f"(hi))
#define UNPACK2(lo, hi, v) asm("mov.b64 {%0, %1}, %2;" : "=f"(lo), "=f"(hi) : "l"(v))
#define FMA2(d, a, b, c)   asm("fma.rn.f32x2 %0, %1, %2, %3;" : "=l"(d) : "l"(a), "l"(b), "l"(c))

__global__ __launch_bounds__(256, 2)
void pt_fused_kernel(const float* __restrict__ points,
                     const float* __restrict__ features,
                     const float* __restrict__ Wq,  const float* __restrict__ bq,
                     const float* __restrict__ Wk,  const float* __restrict__ bk,
                     const float* __restrict__ Wv,  const float* __restrict__ bv,
                     const float* __restrict__ Wp1,
                     const float* __restrict__ p_g, const float* __restrict__ p_b,
                     const float* __restrict__ p_m, const float* __restrict__ p_v,
                     const float* __restrict__ Wp2, const float* __restrict__ bp2,
                     const float* __restrict__ w1_g, const float* __restrict__ w1_b,
                     const float* __restrict__ w1_m, const float* __restrict__ w1_v,
                     const float* __restrict__ Ww1,
                     const float* __restrict__ w2_g, const float* __restrict__ w2_b,
                     const float* __restrict__ w2_m, const float* __restrict__ w2_v,
                     const float* __restrict__ Ww2,  const float* __restrict__ bw2,
                     float* __restrict__ out)
{
    extern __shared__ float sm[];
    float* scratch = sm;                        // 9216
    float* qkv_sh  = scratch + HALO*64;         // 14400
    float* pts_sh  = qkv_sh  + HALO*QPITCH;     // 288
    float* cst     = pts_sh  + HALO*2;
    float2* cM2  = (float2*)(cst);        // 16: (As*s, Bs*s)
    float2* cW2  = (float2*)(cst + 32);   // 16: (Ww1a, Ww1b)
    float*  cP0  = cst + 64;              // 16: bps*s + w1b_eff
    float*  cS   = cst + 80;              // 16: s
    float4* cE4  = (float4*)(cst + 96);   // 8:  (Ww2a, Ww2b, bw2)*log2e
    float4* cR4  = (float4*)(cst + 128);  // 64: (Wp2a, Wp2b, bp2, -)
    float*  misc = cst + 384;             // 12

    const int tid    = threadIdx.x;
    const int bidx   = blockIdx.x;
    const int batch  = bidx >> 7;
    const int tstart = (bidx & 127) * TILE;

    // ---- stage halo features + coords ----
    {
        const float4* fglob = (const float4*)features;
        for (int i = tid; i < HALO*16; i += 256) {
            int h = i >> 4, k4 = i & 15;
            int row = batch*NPTS + ((tstart + h - RAD) & (NPTS - 1));
            ((float4*)scratch)[h*16 + k4] = fglob[row*16 + k4];
        }
        const float2* pglob = (const float2*)points;
        for (int i = tid; i < HALO; i += 256) {
            int row = batch*NPTS + ((tstart + i - RAD) & (NPTS - 1));
            ((float2*)pts_sh)[i] = pglob[row];
        }
    }

    // ---- folded constants ----
    if (tid < 64)
        cR4[tid] = make_float4(Wp2[tid], Wp2[64 + tid], bp2[tid], 0.f);
    if (tid < 16) {
        float As  = Wp2[tid]    + Wp2[16+tid] + Wp2[32+tid] + Wp2[48+tid];
        float Bs  = Wp2[64+tid] + Wp2[80+tid] + Wp2[96+tid] + Wp2[112+tid];
        float bps = bp2[tid] + bp2[16+tid] + bp2[32+tid] + bp2[48+tid];
        float s   = w1_g[tid] * rsqrtf(w1_v[tid] + EPSC);
        float w1beff = w1_b[tid] - w1_m[tid]*s;
        cM2[tid] = make_float2(As*s, Bs*s);
        cW2[tid] = make_float2(Ww1[2*tid], Ww1[2*tid+1]);
        cP0[tid] = bps*s + w1beff;
        cS[tid]  = s;
    }
    if (tid < 8) cE4[tid] = make_float4(Ww2[tid]*L2E, Ww2[8+tid]*L2E, bw2[tid]*L2E, 0.f);
    if (tid >= 32 && tid < 34) {
        int t = tid - 32;
        float s = p_g[t] * rsqrtf(p_v[t] + EPSC);
        misc[4+t] = s; misc[6+t] = p_b[t] - p_m[t]*s;
        float s2 = w2_g[t] * rsqrtf(w2_v[t] + EPSC);
        misc[8+t] = s2; misc[10+t] = w2_b[t] - w2_m[t]*s2;
    }
    if (tid >= 36 && tid < 40) misc[tid - 36] = Wp1[tid - 36];

    // ---- phase-1 weight preload: one channel column per lane, packed f32x2 ----
    const int warp = tid >> 5, lane = tid & 31;
    int cg, sub, npw;
    if (warp < 3)      { cg = 0; sub = warp;     npw = 3; }
    else if (warp < 6) { cg = 1; sub = warp - 3; npw = 3; }
    else               { cg = 2; sub = warp - 6; npw = 2; }
    const int c = cg*32 + lane;

    unsigned long long wp[32];
    float bias;
    if (c < 16) {
        bias = bq[c];
        #pragma unroll
        for (int i = 0; i < 32; ++i) PACK2(wp[i], Wq[(2*i)*16 + c], Wq[(2*i+1)*16 + c]);
    } else if (c < 32) {
        int cc = c - 16; bias = bk[cc];
        #pragma unroll
        for (int i = 0; i < 32; ++i) PACK2(wp[i], Wk[(2*i)*16 + cc], Wk[(2*i+1)*16 + cc]);
    } else {
        int cc = c - 32; bias = bv[cc];
        #pragma unroll
        for (int i = 0; i < 32; ++i) PACK2(wp[i], Wv[(2*i)*64 + cc], Wv[(2*i+1)*64 + cc]);
    }
    __syncthreads();

    const float chan_scale = (c < 32) ? cS[c & 15] : 1.0f;

    // ---- phase 1: q/k/v GEMM via fma.f32x2 -> qkv_sh[p*QPITCH + c] ----
    {
        const int span = HALO / npw;
        const int pend = (sub + 1) * span;
        for (int p = sub * span; p < pend; ++p) {
            const ulonglong2* fr = (const ulonglong2*)(scratch + (p << 6));
            unsigned long long aA = 0ull, aB = 0ull, aC = 0ull, aD = 0ull;
            #pragma unroll
            for (int k2 = 0; k2 < 8; ++k2) {
                ulonglong2 f0 = fr[2*k2];
                ulonglong2 f1 = fr[2*k2 + 1];
                FMA2(aA, f0.x, wp[4*k2    ], aA);
                FMA2(aB, f0.y, wp[4*k2 + 1], aB);
                FMA2(aC, f1.x, wp[4*k2 + 2], aC);
                FMA2(aD, f1.y, wp[4*k2 + 3], aD);
            }
            float x0,x1,x2,x3,x4,x5,x6,x7;
            UNPACK2(x0,x1,aA); UNPACK2(x2,x3,aB); UNPACK2(x4,x5,aC); UNPACK2(x6,x7,aD);
            float s = ((x0+x1)+(x2+x3)) + ((x4+x5)+(x6+x7)) + bias;
            qkv_sh[p*QPITCH + c] = s * chan_scale;
        }
    }
    __syncthreads();

    // ---- phase 2 ----
    const int p    = tid & 127;     // point within tile
    const int half = tid >> 7;      // j-parity in 2a; channel-half in 2b
    const int hme  = p + RAD;

    float vacc[32];
    #pragma unroll
    for (int i = 0; i < 32; ++i) vacc[i] = 0.f;
    float S0[8], S1[8], SE[8];
    #pragma unroll
    for (int i = 0; i < 8; ++i) { S0[i] = 0.f; S1[i] = 0.f; SE[i] = 0.f; }

    const float W00 = misc[0], W01 = misc[1], W10 = misc[2], W11 = misc[3];
    const float ps0 = misc[4], ps1 = misc[5], pb0 = misc[6], pb1 = misc[7];
    const float w2s0 = misc[8], w2s1 = misc[9], w2b0 = misc[10], w2b1 = misc[11];

    #pragma unroll 1
    for (int chunk = 0; chunk < 2; ++chunk) {
        // ---- 2a: MLP+softmax once per (p, j); this thread does j = chunk*8 + 2k + half
        {
            const float px = pts_sh[hme*2], py = pts_sh[hme*2 + 1];
            float P[16];
            {
                const float4* q4 = (const float4*)(qkv_sh + hme*QPITCH);
                #pragma unroll
                for (int m4 = 0; m4 < 4; ++m4) {
                    float4 t = q4[m4];
                    P[4*m4  ] = cP0[4*m4  ] - t.x;
                    P[4*m4+1] = cP0[4*m4+1] - t.y;
                    P[4*m4+2] = cP0[4*m4+2] - t.z;
                    P[4*m4+3] = cP0[4*m4+3] - t.w;
                }
            }
            #pragma unroll 1
            for (int k = 0; k < 4; ++k) {
                const int jj  = chunk*8 + 2*k + half;
                const int off = jj - 8 + (jj >> 3);
                const int h   = hme + off;

                const float dx = pts_sh[h*2]     - px;
                const float dy = pts_sh[h*2 + 1] - py;
                const float h0 = fmaxf(fmaf(dx*W00 + dy*W10, ps0, pb0), 0.f);
                const float h1 = fmaxf(fmaf(dx*W01 + dy*W11, ps1, pb1), 0.f);

                float t0a = 0.f, t0b = 0.f, t1a = 0.f, t1b = 0.f;
                const float4* k4p = (const float4*)(qkv_sh + h*QPITCH + 16);
                const float4* m4p = (const float4*)cM2;
                const float4* w4p = (const float4*)cW2;
                #pragma unroll
                for (int m4 = 0; m4 < 4; ++m4) {
                    float4 kk = k4p[m4];
                    float4 ma = m4p[2*m4], mb = m4p[2*m4+1];
                    float4 wa = w4p[2*m4], wb = w4p[2*m4+1];
                    int m0 = 4*m4;
                    float wr0 = fmaxf(fmaf(h0, ma.x, fmaf(h1, ma.y, kk.x + P[m0  ])), 0.f);
                    float wr1 = fmaxf(fmaf(h0, ma.z, fmaf(h1, ma.w, kk.y + P[m0+1])), 0.f);
                    float wr2 = fmaxf(fmaf(h0, mb.x, fmaf(h1, mb.y, kk.z + P[m0+2])), 0.f);
                    float wr3 = fmaxf(fmaf(h0, mb.z, fmaf(h1, mb.w, kk.w + P[m0+3])), 0.f);
                    t0a = fmaf(wr0, wa.x, t0a);  t1a = fmaf(wr0, wa.y, t1a);
                    t0b = fmaf(wr1, wa.z, t0b);  t1b = fmaf(wr1, wa.w, t1b);
                    t0a = fmaf(wr2, wb.x, t0a);  t1a = fmaf(wr2, wb.y, t1a);
                    t0b = fmaf(wr3, wb.z, t0b);  t1b = fmaf(wr3, wb.w, t1b);
                }
                float t0 = t0a + t0b, t1 = t1a + t1b;
                t0 = fmaxf(fmaf(t0, w2s0, w2b0), 0.f);
                t1 = fmaxf(fmaf(t1, w2s1, w2b1), 0.f);

                float e[8];
                #pragma unroll
                for (int cc = 0; cc < 8; ++cc) {
                    float4 ce = cE4[cc];
                    e[cc] = fmaf(t0, ce.x, fmaf(t1, ce.y, ce.z));   // log2-domain
                }
                float mx = fmaxf(fmaxf(fmaxf(e[0],e[1]), fmaxf(e[2],e[3])),
                                 fmaxf(fmaxf(e[4],e[5]), fmaxf(e[6],e[7])));
                #pragma unroll
                for (int cc = 0; cc < 8; ++cc) e[cc] = exp2f(e[cc] - mx);
                float sA = (e[0]+e[1]) + (e[2]+e[3]);
                float sB = (e[4]+e[5]) + (e[6]+e[7]);
                const float inv = __fdividef(1.0f, sA + sB);
                #pragma unroll
                for (int cc = 0; cc < 8; ++cc) e[cc] *= inv;

                // positional partial sums (this thread's 8 j's across both chunks)
                #pragma unroll
                for (int cc = 0; cc < 8; ++cc) {
                    S0[cc] = fmaf(h0, e[cc], S0[cc]);
                    S1[cc] = fmaf(h1, e[cc], S1[cc]);
                    SE[cc] += e[cc];
                }
                // store normalized e: scratch[cc*1024 + jr*128 + p]
                float* ep = scratch + (jj & 7)*128 + p;
                #pragma unroll
                for (int cc = 0; cc < 8; ++cc) ep[cc*1024] = e[cc];
            }
        }
        __syncthreads();

        // ---- 2b: weighted v accumulation (this thread: 32 channels = half*32..)
        #pragma unroll 2
        for (int jr = 0; jr < 8; ++jr) {
            const int jj  = chunk*8 + jr;
            const int off = jj - 8 + (jj >> 3);
            const int h   = hme + off;
            float e[8];
            const float* ep = scratch + jr*128 + p;
            #pragma unroll
            for (int cc = 0; cc < 8; ++cc) e[cc] = ep[cc*1024];
            const float4* v4 = (const float4*)(qkv_sh + h*QPITCH + 32 + half*32);
            #pragma unroll
            for (int c4 = 0; c4 < 8; ++c4) {
                float4 v = v4[c4];
                vacc[c4*4  ] = fmaf(v.x, e[(c4*4  ) & 7], vacc[c4*4  ]);
                vacc[c4*4+1] = fmaf(v.y, e[(c4*4+1) & 7], vacc[c4*4+1]);
                vacc[c4*4+2] = fmaf(v.z, e[(c4*4+2) & 7], vacc[c4*4+2]);
                vacc[c4*4+3] = fmaf(v.w, e[(c4*4+3) & 7], vacc[c4*4+3]);
            }
        }
        __syncthreads();   // e region reusable (next 2a) / dead (exchange)
    }

    // ---- combine S partials across the two j-parity threads of this point ----
    {
        float* sp = scratch + p*SPITCH + half*24;
        #pragma unroll
        for (int i = 0; i < 8; ++i) { sp[i] = S0[i]; sp[8+i] = S1[i]; sp[16+i] = SE[i]; }
    }
    __syncthreads();
    {
        const float* so = scratch + p*SPITCH + (half^1)*24;
        #pragma unroll
        for (int i = 0; i < 8; ++i) { S0[i] += so[i]; S1[i] += so[8+i]; SE[i] += so[16+i]; }
    }
    // apply factored positional term
    #pragma unroll
    for (int c4 = 0; c4 < 8; ++c4) {
        int cb = half*32 + 4*c4;
        float4 r0 = cR4[cb], r1 = cR4[cb+1], r2 = cR4[cb+2], r3 = cR4[cb+3];
        vacc[c4*4  ] += fmaf(r0.x, S0[(c4*4  )&7], fmaf(r0.y, S1[(c4*4  )&7], r0.z*SE[(c4*4  )&7]));
        vacc[c4*4+1] += fmaf(r1.x, S0[(c4*4+1)&7], fmaf(r1.y, S1[(c4*4+1)&7], r1.z*SE[(c4*4+1)&7]));
        vacc[c4*4+2] += fmaf(r2.x, S0[(c4*4+2)&7], fmaf(r2.y, S1[(c4*4+2)&7], r2.z*SE[(c4*4+2)&7]));
        vacc[c4*4+3] += fmaf(r3.x, S0[(c4*4+3)&7], fmaf(r3.y, S1[(c4*4+3)&7], r3.z*SE[(c4*4+3)&7]));
    }
    __syncthreads();   // S-exchange reads done before staging overwrite

    // ---- stage (pitch 68) and coalesced write-out ----
    {
        float4* st = (float4*)(scratch + p*OPITCH + half*32);
        #pragma unroll
        for (int c4 = 0; c4 < 8; ++c4)
            st[c4] = make_float4(vacc[c4*4], vacc[c4*4+1], vacc[c4*4+2], vacc[c4*4+3]);
    }
    __syncthreads();
    {
        float4* dst = (float4*)(out + (size_t)(batch*NPTS + tstart) * 64);
        for (int i = tid; i < TILE*16; i += 256) {
            int pp = i >> 4, k4 = i & 15;
            dst[i] = ((const float4*)(scratch + pp*OPITCH))[k4];
        }
    }
}

extern "C" void kernel_launch(void* const* d_in, const int* in_sizes, int n_in,
                              void* d_out, int out_size)
{
    const float* points = (const float*)d_in[0];
    const float* feats  = (const float*)d_in[1];
    const float* Wq   = (const float*)d_in[2];
    const float* bq   = (const float*)d_in[3];
    const float* Wk   = (const float*)d_in[4];
    const float* bk   = (const float*)d_in[5];
    const float* Wv   = (const float*)d_in[6];
    const float* bv   = (const float*)d_in[7];
    const float* Wp1  = (const float*)d_in[8];
    const float* p_g  = (const float*)d_in[9];
    const float* p_b  = (const float*)d_in[10];
    const float* p_m  = (const float*)d_in[11];
    const float* p_v  = (const float*)d_in[12];
    const float* Wp2  = (const float*)d_in[13];
    const float* bp2  = (const float*)d_in[14];
    const float* w1_g = (const float*)d_in[15];
    const float* w1_b = (const float*)d_in[16];
    const float* w1_m = (const float*)d_in[17];
    const float* w1_v = (const float*)d_in[18];
    const float* Ww1  = (const float*)d_in[19];
    const float* w2_g = (const float*)d_in[20];
    const float* w2_b = (const float*)d_in[21];
    const float* w2_m = (const float*)d_in[22];
    const float* w2_v = (const float*)d_in[23];
    const float* Ww2  = (const float*)d_in[24];
    const float* bw2  = (const float*)d_in[25];
    float* out = (float*)d_out;

    const int smem_bytes = SMEM_FLOATS * (int)sizeof(float);  // ~97.2 KB
    cudaFuncSetAttribute(pt_fused_kernel,
                         cudaFuncAttributeMaxDynamicSharedMemorySize, smem_bytes);

    const int nblocks = (4 * NPTS) / TILE;   // 512
    pt_fused_kernel<<<nblocks, 256, smem_bytes>>>(
        points, feats, Wq, bq, Wk, bk, Wv, bv, Wp1,
        p_g, p_b, p_m, p_v, Wp2, bp2,
        w1_g, w1_b, w1_m, w1_v, Ww1,
        w2_g, w2_b, w2_m, w2_v, Ww2, bw2, out);
}

// round 6
// speedup vs baseline: 2.2393x; 1.0259x over previous
#include <cuda_runtime.h>

#define NPTS   16384
#define RAD    8
#define TILE   128
#define HALO   (TILE + 2*RAD)   // 144
#define QPITCH 100              // conflict-free float4 (100 mod 32 = 4)
#define OPITCH 68
#define SPITCH 49               // S-exchange pitch (after e region is dead)
#define EPSC   1e-5f
#define L2E    1.44269504088896340736f

// scratch (9216 floats): features (phase1) -> e-pairs u64[cpair*1024+jr*128+p]
//                        (8192 floats) -> S-exchange (pitch 49) -> out staging
#define SMEM_FLOATS (HALO*64 + HALO*QPITCH + HALO*2 + 396)

#define PACK2(dst, lo, hi) asm("mov.b64 %0, {%1, %2};" : "=l"(dst) : "f"(lo), "f"(hi))
#define UNPACK2(lo, hi, v) asm("mov.b64 {%0, %1}, %2;" : "=f"(lo), "=f"(hi) : "l"(v))
#define FMA2(d, a, b, c)   asm("fma.rn.f32x2 %0, %1, %2, %3;" : "=l"(d) : "l"(a), "l"(b), "l"(c))

__global__ __launch_bounds__(256, 2)
void pt_fused_kernel(const float* __restrict__ points,
                     const float* __restrict__ features,
                     const float* __restrict__ Wq,  const float* __restrict__ bq,
                     const float* __restrict__ Wk,  const float* __restrict__ bk,
                     const float* __restrict__ Wv,  const float* __restrict__ bv,
                     const float* __restrict__ Wp1,
                     const float* __restrict__ p_g, const float* __restrict__ p_b,
                     const float* __restrict__ p_m, const float* __restrict__ p_v,
                     const float* __restrict__ Wp2, const float* __restrict__ bp2,
                     const float* __restrict__ w1_g, const float* __restrict__ w1_b,
                     const float* __restrict__ w1_m, const float* __restrict__ w1_v,
                     const float* __restrict__ Ww1,
                     const float* __restrict__ w2_g, const float* __restrict__ w2_b,
                     const float* __restrict__ w2_m, const float* __restrict__ w2_v,
                     const float* __restrict__ Ww2,  const float* __restrict__ bw2,
                     float* __restrict__ out)
{
    extern __shared__ float sm[];
    float* scratch = sm;                        // 9216
    float* qkv_sh  = scratch + HALO*64;         // 14400
    float* pts_sh  = qkv_sh  + HALO*QPITCH;     // 288
    float* cst     = pts_sh  + HALO*2;
    float2* cM2  = (float2*)(cst);        // 16: (As*s, Bs*s)
    float2* cW2  = (float2*)(cst + 32);   // 16: (Ww1a, Ww1b)
    float*  cP0  = cst + 64;              // 16: bps*s + w1b_eff
    float*  cS   = cst + 80;              // 16: s
    float4* cE4  = (float4*)(cst + 96);   // 8:  (Ww2a, Ww2b, bw2)*log2e
    float4* cR4  = (float4*)(cst + 128);  // 64: (Wp2a, Wp2b, bp2, -)
    float*  misc = cst + 384;             // 12

    const int tid    = threadIdx.x;
    const int bidx   = blockIdx.x;
    const int batch  = bidx >> 7;
    const int tstart = (bidx & 127) * TILE;

    // ---- stage halo features + coords ----
    {
        const float4* fglob = (const float4*)features;
        for (int i = tid; i < HALO*16; i += 256) {
            int h = i >> 4, k4 = i & 15;
            int row = batch*NPTS + ((tstart + h - RAD) & (NPTS - 1));
            ((float4*)scratch)[h*16 + k4] = fglob[row*16 + k4];
        }
        const float2* pglob = (const float2*)points;
        for (int i = tid; i < HALO; i += 256) {
            int row = batch*NPTS + ((tstart + i - RAD) & (NPTS - 1));
            ((float2*)pts_sh)[i] = pglob[row];
        }
    }

    // ---- folded constants ----
    if (tid < 64)
        cR4[tid] = make_float4(Wp2[tid], Wp2[64 + tid], bp2[tid], 0.f);
    if (tid < 16) {
        float As  = Wp2[tid]    + Wp2[16+tid] + Wp2[32+tid] + Wp2[48+tid];
        float Bs  = Wp2[64+tid] + Wp2[80+tid] + Wp2[96+tid] + Wp2[112+tid];
        float bps = bp2[tid] + bp2[16+tid] + bp2[32+tid] + bp2[48+tid];
        float s   = w1_g[tid] * rsqrtf(w1_v[tid] + EPSC);
        float w1beff = w1_b[tid] - w1_m[tid]*s;
        cM2[tid] = make_float2(As*s, Bs*s);
        cW2[tid] = make_float2(Ww1[2*tid], Ww1[2*tid+1]);
        cP0[tid] = bps*s + w1beff;
        cS[tid]  = s;
    }
    if (tid < 8) cE4[tid] = make_float4(Ww2[tid]*L2E, Ww2[8+tid]*L2E, bw2[tid]*L2E, 0.f);
    if (tid >= 32 && tid < 34) {
        int t = tid - 32;
        float s = p_g[t] * rsqrtf(p_v[t] + EPSC);
        misc[4+t] = s; misc[6+t] = p_b[t] - p_m[t]*s;
        float s2 = w2_g[t] * rsqrtf(w2_v[t] + EPSC);
        misc[8+t] = s2; misc[10+t] = w2_b[t] - w2_m[t]*s2;
    }
    if (tid >= 36 && tid < 40) misc[tid - 36] = Wp1[tid - 36];

    // ---- phase-1 weight preload: one channel column per lane, packed f32x2 ----
    const int warp = tid >> 5, lane = tid & 31;
    int cg, sub, npw;
    if (warp < 3)      { cg = 0; sub = warp;     npw = 3; }
    else if (warp < 6) { cg = 1; sub = warp - 3; npw = 3; }
    else               { cg = 2; sub = warp - 6; npw = 2; }
    const int c = cg*32 + lane;

    unsigned long long wp[32];
    float bias;
    if (c < 16) {
        bias = bq[c];
        #pragma unroll
        for (int i = 0; i < 32; ++i) PACK2(wp[i], Wq[(2*i)*16 + c], Wq[(2*i+1)*16 + c]);
    } else if (c < 32) {
        int cc = c - 16; bias = bk[cc];
        #pragma unroll
        for (int i = 0; i < 32; ++i) PACK2(wp[i], Wk[(2*i)*16 + cc], Wk[(2*i+1)*16 + cc]);
    } else {
        int cc = c - 32; bias = bv[cc];
        #pragma unroll
        for (int i = 0; i < 32; ++i) PACK2(wp[i], Wv[(2*i)*64 + cc], Wv[(2*i+1)*64 + cc]);
    }
    __syncthreads();

    const float chan_scale = (c < 32) ? cS[c & 15] : 1.0f;

    // ---- phase 1: q/k/v GEMM via fma.f32x2 -> qkv_sh[p*QPITCH + c] ----
    {
        const int span = HALO / npw;
        const int pend = (sub + 1) * span;
        #pragma unroll 2
        for (int p = sub * span; p < pend; ++p) {
            const ulonglong2* fr = (const ulonglong2*)(scratch + (p << 6));
            unsigned long long aA = 0ull, aB = 0ull, aC = 0ull, aD = 0ull;
            #pragma unroll
            for (int k2 = 0; k2 < 8; ++k2) {
                ulonglong2 f0 = fr[2*k2];
                ulonglong2 f1 = fr[2*k2 + 1];
                FMA2(aA, f0.x, wp[4*k2    ], aA);
                FMA2(aB, f0.y, wp[4*k2 + 1], aB);
                FMA2(aC, f1.x, wp[4*k2 + 2], aC);
                FMA2(aD, f1.y, wp[4*k2 + 3], aD);
            }
            float x0,x1,x2,x3,x4,x5,x6,x7;
            UNPACK2(x0,x1,aA); UNPACK2(x2,x3,aB); UNPACK2(x4,x5,aC); UNPACK2(x6,x7,aD);
            float s = ((x0+x1)+(x2+x3)) + ((x4+x5)+(x6+x7)) + bias;
            qkv_sh[p*QPITCH + c] = s * chan_scale;
        }
    }
    __syncthreads();

    // ---- phase 2 ----
    const int p    = tid & 127;     // point within tile
    const int half = tid >> 7;      // j-parity in 2a; channel-half in 2b
    const int hme  = p + RAD;

    unsigned long long vacc2[16];
    #pragma unroll
    for (int i = 0; i < 16; ++i) vacc2[i] = 0ull;
    float S0[8], S1[8], SE[8];
    #pragma unroll
    for (int i = 0; i < 8; ++i) { S0[i] = 0.f; S1[i] = 0.f; SE[i] = 0.f; }

    const float W00 = misc[0], W01 = misc[1], W10 = misc[2], W11 = misc[3];
    const float ps0 = misc[4], ps1 = misc[5], pb0 = misc[6], pb1 = misc[7];
    const float w2s0 = misc[8], w2s1 = misc[9], w2b0 = misc[10], w2b1 = misc[11];

    #pragma unroll 1
    for (int chunk = 0; chunk < 2; ++chunk) {
        // ---- 2a: MLP+softmax once per (p, j); this thread: j = chunk*8 + 2k + half
        {
            const float2 pme = ((const float2*)pts_sh)[hme];
            float P[16];
            {
                const float4* q4 = (const float4*)(qkv_sh + hme*QPITCH);
                #pragma unroll
                for (int m4 = 0; m4 < 4; ++m4) {
                    float4 t = q4[m4];
                    P[4*m4  ] = cP0[4*m4  ] - t.x;
                    P[4*m4+1] = cP0[4*m4+1] - t.y;
                    P[4*m4+2] = cP0[4*m4+2] - t.z;
                    P[4*m4+3] = cP0[4*m4+3] - t.w;
                }
            }
            #pragma unroll 1
            for (int k = 0; k < 4; ++k) {
                const int jj  = chunk*8 + 2*k + half;
                const int off = jj - 8 + (jj >> 3);
                const int h   = hme + off;

                const float2 pn = ((const float2*)pts_sh)[h];
                const float dx = pn.x - pme.x;
                const float dy = pn.y - pme.y;
                const float h0 = fmaxf(fmaf(dx*W00 + dy*W10, ps0, pb0), 0.f);
                const float h1 = fmaxf(fmaf(dx*W01 + dy*W11, ps1, pb1), 0.f);

                float t0a = 0.f, t0b = 0.f, t1a = 0.f, t1b = 0.f;
                const float4* k4p = (const float4*)(qkv_sh + h*QPITCH + 16);
                const float4* m4p = (const float4*)cM2;
                const float4* w4p = (const float4*)cW2;
                #pragma unroll
                for (int m4 = 0; m4 < 4; ++m4) {
                    float4 kk = k4p[m4];
                    float4 ma = m4p[2*m4], mb = m4p[2*m4+1];
                    float4 wa = w4p[2*m4], wb = w4p[2*m4+1];
                    int m0 = 4*m4;
                    float wr0 = fmaxf(fmaf(h0, ma.x, fmaf(h1, ma.y, kk.x + P[m0  ])), 0.f);
                    float wr1 = fmaxf(fmaf(h0, ma.z, fmaf(h1, ma.w, kk.y + P[m0+1])), 0.f);
                    float wr2 = fmaxf(fmaf(h0, mb.x, fmaf(h1, mb.y, kk.z + P[m0+2])), 0.f);
                    float wr3 = fmaxf(fmaf(h0, mb.z, fmaf(h1, mb.w, kk.w + P[m0+3])), 0.f);
                    t0a = fmaf(wr0, wa.x, t0a);  t1a = fmaf(wr0, wa.y, t1a);
                    t0b = fmaf(wr1, wa.z, t0b);  t1b = fmaf(wr1, wa.w, t1b);
                    t0a = fmaf(wr2, wb.x, t0a);  t1a = fmaf(wr2, wb.y, t1a);
                    t0b = fmaf(wr3, wb.z, t0b);  t1b = fmaf(wr3, wb.w, t1b);
                }
                float t0 = t0a + t0b, t1 = t1a + t1b;
                t0 = fmaxf(fmaf(t0, w2s0, w2b0), 0.f);
                t1 = fmaxf(fmaf(t1, w2s1, w2b1), 0.f);

                float e[8];
                #pragma unroll
                for (int cc = 0; cc < 8; ++cc) {
                    float4 ce = cE4[cc];
                    e[cc] = fmaf(t0, ce.x, fmaf(t1, ce.y, ce.z));   // log2-domain
                }
                float mx = fmaxf(fmaxf(fmaxf(e[0],e[1]), fmaxf(e[2],e[3])),
                                 fmaxf(fmaxf(e[4],e[5]), fmaxf(e[6],e[7])));
                #pragma unroll
                for (int cc = 0; cc < 8; ++cc) e[cc] = exp2f(e[cc] - mx);
                float sA = (e[0]+e[1]) + (e[2]+e[3]);
                float sB = (e[4]+e[5]) + (e[6]+e[7]);
                const float inv = __fdividef(1.0f, sA + sB);
                #pragma unroll
                for (int cc = 0; cc < 8; ++cc) e[cc] *= inv;

                // positional partial sums (this thread's 8 j's across both chunks)
                #pragma unroll
                for (int cc = 0; cc < 8; ++cc) {
                    S0[cc] = fmaf(h0, e[cc], S0[cc]);
                    S1[cc] = fmaf(h1, e[cc], S1[cc]);
                    SE[cc] += e[cc];
                }
                // store e as pairs: u64 scratch[cpair*1024 + jr*128 + p]
                {
                    float2* ep = (float2*)scratch + (jj & 7)*128 + p;
                    ep[0]      = make_float2(e[0], e[1]);
                    ep[1024]   = make_float2(e[2], e[3]);
                    ep[2048]   = make_float2(e[4], e[5]);
                    ep[3072]   = make_float2(e[6], e[7]);
                }
            }
        }
        __syncthreads();

        // ---- 2b: packed-f32x2 weighted v accumulation (32 channels/thread) ----
        #pragma unroll 2
        for (int jr = 0; jr < 8; ++jr) {
            const int jj  = chunk*8 + jr;
            const int off = jj - 8 + (jj >> 3);
            const int h   = hme + off;
            const unsigned long long* ep = (const unsigned long long*)scratch + jr*128 + p;
            unsigned long long e2[4];
            e2[0] = ep[0]; e2[1] = ep[1024]; e2[2] = ep[2048]; e2[3] = ep[3072];
            const ulonglong2* v2 = (const ulonglong2*)(qkv_sh + h*QPITCH + 32 + half*32);
            #pragma unroll
            for (int i = 0; i < 8; ++i) {
                ulonglong2 v = v2[i];
                FMA2(vacc2[2*i  ], v.x, e2[(2*i  ) & 3], vacc2[2*i  ]);
                FMA2(vacc2[2*i+1], v.y, e2[(2*i+1) & 3], vacc2[2*i+1]);
            }
        }
        __syncthreads();   // e region reusable (next 2a) / dead (exchange)
    }

    // ---- unpack accumulators ----
    float va[32];
    #pragma unroll
    for (int t = 0; t < 16; ++t) UNPACK2(va[2*t], va[2*t+1], vacc2[t]);

    // ---- combine S partials across the two j-parity threads of this point ----
    {
        float* sp = scratch + p*SPITCH + half*24;
        #pragma unroll
        for (int i = 0; i < 8; ++i) { sp[i] = S0[i]; sp[8+i] = S1[i]; sp[16+i] = SE[i]; }
    }
    __syncthreads();
    {
        const float* so = scratch + p*SPITCH + (half^1)*24;
        #pragma unroll
        for (int i = 0; i < 8; ++i) { S0[i] += so[i]; S1[i] += so[8+i]; SE[i] += so[16+i]; }
    }
    // apply factored positional term
    #pragma unroll
    for (int c4 = 0; c4 < 8; ++c4) {
        int cb = half*32 + 4*c4;
        float4 r0 = cR4[cb], r1 = cR4[cb+1], r2 = cR4[cb+2], r3 = cR4[cb+3];
        va[c4*4  ] += fmaf(r0.x, S0[(c4*4  )&7], fmaf(r0.y, S1[(c4*4  )&7], r0.z*SE[(c4*4  )&7]));
        va[c4*4+1] += fmaf(r1.x, S0[(c4*4+1)&7], fmaf(r1.y, S1[(c4*4+1)&7], r1.z*SE[(c4*4+1)&7]));
        va[c4*4+2] += fmaf(r2.x, S0[(c4*4+2)&7], fmaf(r2.y, S1[(c4*4+2)&7], r2.z*SE[(c4*4+2)&7]));
        va[c4*4+3] += fmaf(r3.x, S0[(c4*4+3)&7], fmaf(r3.y, S1[(c4*4+3)&7], r3.z*SE[(c4*4+3)&7]));
    }
    __syncthreads();   // S-exchange reads done before staging overwrite

    // ---- stage (pitch 68) and coalesced write-out ----
    {
        float4* st = (float4*)(scratch + p*OPITCH + half*32);
        #pragma unroll
        for (int c4 = 0; c4 < 8; ++c4)
            st[c4] = make_float4(va[c4*4], va[c4*4+1], va[c4*4+2], va[c4*4+3]);
    }
    __syncthreads();
    {
        float4* dst = (float4*)(out + (size_t)(batch*NPTS + tstart) * 64);
        for (int i = tid; i < TILE*16; i += 256) {
            int pp = i >> 4, k4 = i & 15;
            dst[i] = ((const float4*)(scratch + pp*OPITCH))[k4];
        }
    }
}

extern "C" void kernel_launch(void* const* d_in, const int* in_sizes, int n_in,
                              void* d_out, int out_size)
{
    const float* points = (const float*)d_in[0];
    const float* feats  = (const float*)d_in[1];
    const float* Wq   = (const float*)d_in[2];
    const float* bq   = (const float*)d_in[3];
    const float* Wk   = (const float*)d_in[4];
    const float* bk   = (const float*)d_in[5];
    const float* Wv   = (const float*)d_in[6];
    const float* bv   = (const float*)d_in[7];
    const float* Wp1  = (const float*)d_in[8];
    const float* p_g  = (const float*)d_in[9];
    const float* p_b  = (const float*)d_in[10];
    const float* p_m  = (const float*)d_in[11];
    const float* p_v  = (const float*)d_in[12];
    const float* Wp2  = (const float*)d_in[13];
    const float* bp2  = (const float*)d_in[14];
    const float* w1_g = (const float*)d_in[15];
    const float* w1_b = (const float*)d_in[16];
    const float* w1_m = (const float*)d_in[17];
    const float* w1_v = (const float*)d_in[18];
    const float* Ww1  = (const float*)d_in[19];
    const float* w2_g = (const float*)d_in[20];
    const float* w2_b = (const float*)d_in[21];
    const float* w2_m = (const float*)d_in[22];
    const float* w2_v = (const float*)d_in[23];
    const float* Ww2  = (const float*)d_in[24];
    const float* bw2  = (const float*)d_in[25];
    float* out = (float*)d_out;

    const int smem_bytes = SMEM_FLOATS * (int)sizeof(float);  // ~97.2 KB
    cudaFuncSetAttribute(pt_fused_kernel,
                         cudaFuncAttributeMaxDynamicSharedMemorySize, smem_bytes);

    const int nblocks = (4 * NPTS) / TILE;   // 512
    pt_fused_kernel<<<nblocks, 256, smem_bytes>>>(
        points, feats, Wq, bq, Wk, bk, Wv, bv, Wp1,
        p_g, p_b, p_m, p_v, Wp2, bp2,
        w1_g, w1_b, w1_m, w1_v, Ww1,
        w2_g, w2_b, w2_m, w2_v, Ww2, bw2, out);
}